// round 1
// baseline (speedup 1.0000x reference)
#include <cuda_runtime.h>
#include <math.h>

// ---------------- problem constants ----------------
#define B_IMG  32
#define C_IN   256
#define HWDIM  56
#define PIX_PER_IMG (HWDIM*HWDIM)      // 3136
#define NPIX   (B_IMG*PIX_PER_IMG)     // 100352
#define N_TOK  49
#define NH     8
#define DH     32
#define DE     1024
#define NWIN   (B_IMG*64)              // 2048
#define GEMM1_N 1536
#define GEMM1_K 256
#define GEMM2_N 256
#define GEMM2_K 1024

// ---------------- scratch (device globals; no allocations allowed) ----------------
__device__ float g_mean[NPIX];
__device__ float g_rstd[NPIX];
__device__ float g_q[NWIN*NH*N_TOK*DH];            // [wi][head][n][d], q pre-scaled
__device__ float g_k[NWIN*NH*N_TOK*DH];            // [wi][head][n][d]
__device__ float g_v[(size_t)NWIN*N_TOK*DE];       // [wi][n][1024]; [0:512] becomes attn out

__device__ __forceinline__ float gelu_exact(float x) {
    return 0.5f * x * (1.0f + erff(x * 0.7071067811865476f));
}

// ================= kernel 1: pre-LN stats (per-pixel over 256 channels) =================
__global__ __launch_bounds__(256) void ln_stats_kernel(const float* __restrict__ x) {
    int pix0 = blockIdx.x * 64;            // 3136 % 64 == 0, never crosses an image
    int px = threadIdx.x & 63;
    int cg = threadIdx.x >> 6;             // 0..3
    int b  = pix0 / PIX_PER_IMG;
    int hw = pix0 % PIX_PER_IMG;
    const float* xb = x + (size_t)b * C_IN * PIX_PER_IMG + hw;
    float s = 0.f, ss = 0.f;
    for (int c = cg; c < C_IN; c += 4) {
        float v = xb[(size_t)c * PIX_PER_IMG + px];
        s += v; ss += v * v;
    }
    __shared__ float sh_s[4][64], sh_ss[4][64];
    sh_s[cg][px] = s; sh_ss[cg][px] = ss;
    __syncthreads();
    if (threadIdx.x < 64) {
        float t = 0.f, tt = 0.f;
        #pragma unroll
        for (int i = 0; i < 4; i++) { t += sh_s[i][threadIdx.x]; tt += sh_ss[i][threadIdx.x]; }
        float mean = t * (1.0f / 256.0f);
        float var  = tt * (1.0f / 256.0f) - mean * mean;
        g_mean[pix0 + threadIdx.x] = mean;
        g_rstd[pix0 + threadIdx.x] = rsqrtf(var + 1e-5f);
    }
}

// ================= kernel 2: GEMM1  (LN(x) @ [qk_w; v_w]^T) =================
// M = NPIX pixels (raster order), N = 1536, K = 256. BM=BN=128, BK=8, 256 thr, 8x8/thr.
__global__ __launch_bounds__(256) void gemm1_kernel(
    const float* __restrict__ x,
    const float* __restrict__ pre_g, const float* __restrict__ pre_b,
    const float* __restrict__ qk_w,  const float* __restrict__ qk_b,
    const float* __restrict__ v_w,   const float* __restrict__ v_b)
{
    const int BK = 8;
    __shared__ float As[BK][128];
    __shared__ float Ws[BK][132];

    int mb = blockIdx.y * 128;
    int nb = blockIdx.x * 128;
    int tid = threadIdx.x;

    // --- A loader mapping (float4 along pixel dim) ---
    int a_c = tid >> 5;                 // 0..7 (k within tile)
    int a_m = (tid & 31) * 4;           // 0..124
    int m4  = mb + a_m;                 // float4 never crosses image (3136 % 4 == 0)
    int bimg = m4 / PIX_PER_IMG;
    int hw4  = m4 % PIX_PER_IMG;
    const float* xptr = x + (size_t)bimg * C_IN * PIX_PER_IMG + hw4;
    float4 mean4 = *(const float4*)(g_mean + m4);
    float4 rstd4 = *(const float4*)(g_rstd + m4);

    // --- W loader mapping ---
    int w_o = tid >> 1;                 // 0..127
    int w_c = (tid & 1) * 4;            // 0 or 4
    int oo  = nb + w_o;
    const float* wrow = (oo < 512) ? (qk_w + (size_t)oo * 256)
                                   : (v_w + (size_t)(oo - 512) * 256);

    int tx = tid & 15;                  // N dir
    int ty = tid >> 4;                  // M dir

    float acc[8][8];
    #pragma unroll
    for (int i = 0; i < 8; i++)
        #pragma unroll
        for (int j = 0; j < 8; j++) acc[i][j] = 0.f;

    // prologue loads
    float4 a_nx = *(const float4*)(xptr + (size_t)a_c * PIX_PER_IMG);
    float4 w_nx = *(const float4*)(wrow + w_c);
    float  gc = pre_g[a_c], bc = pre_b[a_c];

    const int ITERS = GEMM1_K / BK;     // 32
    for (int kt = 0; kt < ITERS; kt++) {
        // store (with LN applied to A)
        float4 av;
        av.x = (a_nx.x - mean4.x) * rstd4.x * gc + bc;
        av.y = (a_nx.y - mean4.y) * rstd4.y * gc + bc;
        av.z = (a_nx.z - mean4.z) * rstd4.z * gc + bc;
        av.w = (a_nx.w - mean4.w) * rstd4.w * gc + bc;
        *(float4*)&As[a_c][a_m] = av;
        Ws[w_c + 0][w_o] = w_nx.x;
        Ws[w_c + 1][w_o] = w_nx.y;
        Ws[w_c + 2][w_o] = w_nx.z;
        Ws[w_c + 3][w_o] = w_nx.w;
        __syncthreads();

        if (kt + 1 < ITERS) {
            int k0 = (kt + 1) * BK;
            int c  = k0 + a_c;
            a_nx = *(const float4*)(xptr + (size_t)c * PIX_PER_IMG);
            gc = pre_g[c]; bc = pre_b[c];
            w_nx = *(const float4*)(wrow + k0 + w_c);
        }

        #pragma unroll
        for (int kk = 0; kk < BK; kk++) {
            float af[8], wf[8];
            #pragma unroll
            for (int i = 0; i < 4; i++) {
                af[i]     = As[kk][ty * 4 + i];
                af[4 + i] = As[kk][64 + ty * 4 + i];
                wf[i]     = Ws[kk][tx * 4 + i];
                wf[4 + i] = Ws[kk][64 + tx * 4 + i];
            }
            #pragma unroll
            for (int i = 0; i < 8; i++)
                #pragma unroll
                for (int j = 0; j < 8; j++) acc[i][j] += af[i] * wf[j];
        }
        __syncthreads();
    }

    // --- epilogue: scatter into q / k / v (window layout) ---
    #pragma unroll
    for (int i = 0; i < 8; i++) {
        int ml = (i < 4) ? (ty * 4 + i) : (64 + ty * 4 + (i - 4));
        int m  = mb + ml;
        int b  = m / PIX_PER_IMG;
        int hw = m % PIX_PER_IMG;
        int h = hw / HWDIM, w = hw % HWDIM;
        int wi = b * 64 + (h & 7) * 8 + (w & 7);   // dilated window index
        int n  = (h >> 3) * 7 + (w >> 3);          // token within window
        #pragma unroll
        for (int j = 0; j < 8; j++) {
            int o = nb + ((j < 4) ? (tx * 4 + j) : (64 + tx * 4 + (j - 4)));
            float val = acc[i][j];
            if (o < 256) {
                val += qk_b[o];
                g_q[(((size_t)wi * 8 + (o >> 5)) * 49 + n) * 32 + (o & 31)] =
                    val * 0.17677669529663687f;  // 32^-0.5 folded into q
            } else if (o < 512) {
                val += qk_b[o];
                int q2 = o - 256;
                g_k[(((size_t)wi * 8 + (q2 >> 5)) * 49 + n) * 32 + (q2 & 31)] = val;
            } else {
                int vo = o - 512;
                val += v_b[vo];
                g_v[((size_t)wi * 49 + n) * 1024 + vo] = val;
            }
        }
    }
}

// ================= kernel 3: windowed attention, one CTA per (window, head) =================
__global__ __launch_bounds__(128) void attn_kernel(const float* __restrict__ rpb) {
    int head = blockIdx.x;
    int wi   = blockIdx.y;
    int wp   = wi & 63;
    int tid  = threadIdx.x;

    __shared__ float Qs[49][33];
    __shared__ float Ks[49][33];
    __shared__ float Vs[49][64];
    __shared__ float Ss[49 * 49];
    __shared__ float rpbs[169];

    const float* qbase = g_q + ((size_t)wi * 8 + head) * 49 * 32;
    const float* kbase = g_k + ((size_t)wi * 8 + head) * 49 * 32;
    float* vbase = g_v + (size_t)wi * 49 * 1024 + head * 64;

    for (int i = tid; i < 49 * 32; i += 128) {
        Qs[i >> 5][i & 31] = qbase[i];
        Ks[i >> 5][i & 31] = kbase[i];
    }
    for (int i = tid; i < 169; i += 128)
        rpbs[i] = rpb[((size_t)wp * 169 + i) * 8 + head];
    for (int i = tid; i < 49 * 64; i += 128) {
        int n = i >> 6, vh = i & 63;
        Vs[n][vh] = vbase[(size_t)n * 1024 + vh];
    }
    __syncthreads();

    // scores + bias
    for (int i = tid; i < 49 * 49; i += 128) {
        int n = i / 49, m = i % 49;
        float s = 0.f;
        #pragma unroll
        for (int d = 0; d < 32; d++) s += Qs[n][d] * Ks[m][d];
        int i1 = n / 7, j1 = n % 7, i2 = m / 7, j2 = m % 7;
        s += rpbs[(i1 - i2 + 6) * 13 + (j1 - j2 + 6)];
        Ss[i] = s;
    }
    __syncthreads();

    // softmax: one thread per row
    if (tid < 49) {
        float* row = Ss + tid * 49;
        float mx = -1e30f;
        #pragma unroll 7
        for (int m = 0; m < 49; m++) mx = fmaxf(mx, row[m]);
        float sum = 0.f;
        #pragma unroll 7
        for (int m = 0; m < 49; m++) { float e = __expf(row[m] - mx); row[m] = e; sum += e; }
        float inv = 1.0f / sum;
        #pragma unroll 7
        for (int m = 0; m < 49; m++) row[m] *= inv;
    }
    __syncthreads();

    // O = S @ V, written in place over V_attn slice
    for (int i = tid; i < 49 * 64; i += 128) {
        int n = i >> 6, vh = i & 63;
        float o = 0.f;
        #pragma unroll 7
        for (int m = 0; m < 49; m++) o += Ss[n * 49 + m] * Vs[m][vh];
        vbase[(size_t)n * 1024 + vh] = o;
    }
}

// ================= kernel 4: post-LN (first 512) + GELU (all 1024), in place =================
__global__ __launch_bounds__(256) void ln2_gelu_kernel(
    const float* __restrict__ pg, const float* __restrict__ pb)
{
    size_t row = blockIdx.x;
    float* p = g_v + row * 1024;
    int tid = threadIdx.x;
    float4 v = reinterpret_cast<float4*>(p)[tid];

    float s = 0.f, ss = 0.f;
    if (tid < 128) {
        s  = v.x + v.y + v.z + v.w;
        ss = v.x * v.x + v.y * v.y + v.z * v.z + v.w * v.w;
    }
    #pragma unroll
    for (int off = 16; off; off >>= 1) {
        s  += __shfl_down_sync(0xffffffffu, s, off);
        ss += __shfl_down_sync(0xffffffffu, ss, off);
    }
    __shared__ float sh[16];
    int wid = tid >> 5, lane = tid & 31;
    if (lane == 0) { sh[wid] = s; sh[8 + wid] = ss; }
    __syncthreads();
    if (tid == 0) {
        float S = 0.f, SS = 0.f;
        #pragma unroll
        for (int i = 0; i < 8; i++) { S += sh[i]; SS += sh[8 + i]; }
        float mean = S * (1.0f / 512.0f);
        float var  = SS * (1.0f / 512.0f) - mean * mean;
        sh[0] = mean; sh[1] = rsqrtf(var + 1e-5f);
    }
    __syncthreads();
    float mean = sh[0], rstd = sh[1];

    if (tid < 128) {
        int c = tid * 4;
        v.x = (v.x - mean) * rstd * pg[c + 0] + pb[c + 0];
        v.y = (v.y - mean) * rstd * pg[c + 1] + pb[c + 1];
        v.z = (v.z - mean) * rstd * pg[c + 2] + pb[c + 2];
        v.w = (v.w - mean) * rstd * pg[c + 3] + pb[c + 3];
    }
    v.x = gelu_exact(v.x); v.y = gelu_exact(v.y);
    v.z = gelu_exact(v.z); v.w = gelu_exact(v.w);
    reinterpret_cast<float4*>(p)[tid] = v;
}

// ================= kernel 5: GEMM2  (xg @ proj_w^T) + bias + residual + roll(2,2) =================
// M ordered as m2 = wi*49 + n (rows of g_v). N = 256, K = 1024.
__global__ __launch_bounds__(256) void gemm2_kernel(
    const float* __restrict__ x,
    const float* __restrict__ proj_w, const float* __restrict__ proj_b,
    float* __restrict__ out)
{
    const int BK = 8;
    __shared__ float As[BK][128];
    __shared__ float Ws[BK][132];

    int mb = blockIdx.y * 128;
    int nb = blockIdx.x * 128;
    int tid = threadIdx.x;

    int a_m = tid & 127;
    int a_c = (tid >> 7) * 4;           // 0 or 4
    const float* arow = g_v + (size_t)(mb + a_m) * 1024 + a_c;

    int w_o = tid >> 1;
    int w_c = (tid & 1) * 4;
    const float* wrow = proj_w + (size_t)(nb + w_o) * 1024;

    int tx = tid & 15;
    int ty = tid >> 4;

    float acc[8][8];
    #pragma unroll
    for (int i = 0; i < 8; i++)
        #pragma unroll
        for (int j = 0; j < 8; j++) acc[i][j] = 0.f;

    float4 a_nx = *(const float4*)(arow);
    float4 w_nx = *(const float4*)(wrow + w_c);

    const int ITERS = GEMM2_K / BK;     // 128
    for (int kt = 0; kt < ITERS; kt++) {
        As[a_c + 0][a_m] = a_nx.x;
        As[a_c + 1][a_m] = a_nx.y;
        As[a_c + 2][a_m] = a_nx.z;
        As[a_c + 3][a_m] = a_nx.w;
        Ws[w_c + 0][w_o] = w_nx.x;
        Ws[w_c + 1][w_o] = w_nx.y;
        Ws[w_c + 2][w_o] = w_nx.z;
        Ws[w_c + 3][w_o] = w_nx.w;
        __syncthreads();

        if (kt + 1 < ITERS) {
            int k0 = (kt + 1) * BK;
            a_nx = *(const float4*)(arow + k0);
            w_nx = *(const float4*)(wrow + k0 + w_c);
        }

        #pragma unroll
        for (int kk = 0; kk < BK; kk++) {
            float af[8], wf[8];
            #pragma unroll
            for (int i = 0; i < 4; i++) {
                af[i]     = As[kk][ty * 4 + i];
                af[4 + i] = As[kk][64 + ty * 4 + i];
                wf[i]     = Ws[kk][tx * 4 + i];
                wf[4 + i] = Ws[kk][64 + tx * 4 + i];
            }
            #pragma unroll
            for (int i = 0; i < 8; i++)
                #pragma unroll
                for (int j = 0; j < 8; j++) acc[i][j] += af[i] * wf[j];
        }
        __syncthreads();
    }

    // epilogue: + proj_b + shortcut, write rolled
    #pragma unroll
    for (int i = 0; i < 8; i++) {
        int ml = (i < 4) ? (ty * 4 + i) : (64 + ty * 4 + (i - 4));
        int m2 = mb + ml;
        int wi = m2 / 49, n = m2 % 49;
        int b = wi >> 6, wp = wi & 63;
        int h = (n / 7) * 8 + (wp >> 3);
        int w = (n % 7) * 8 + (wp & 7);
        int h2 = h + 2; if (h2 >= 56) h2 -= 56;
        int w2 = w + 2; if (w2 >= 56) w2 -= 56;
        size_t in_px  = (size_t)h  * 56 + w;
        size_t out_px = (size_t)h2 * 56 + w2;
        #pragma unroll
        for (int j = 0; j < 8; j++) {
            int o = nb + ((j < 4) ? (tx * 4 + j) : (64 + tx * 4 + (j - 4)));
            size_t chbase = ((size_t)b * 256 + o) * PIX_PER_IMG;
            out[chbase + out_px] = acc[i][j] + proj_b[o] + x[chbase + in_px];
        }
    }
}

// ================= launch =================
extern "C" void kernel_launch(void* const* d_in, const int* in_sizes, int n_in,
                              void* d_out, int out_size) {
    const float* x      = (const float*)d_in[0];
    const float* pre_g  = (const float*)d_in[1];
    const float* pre_b  = (const float*)d_in[2];
    const float* post_g = (const float*)d_in[3];
    const float* post_b = (const float*)d_in[4];
    const float* qk_w   = (const float*)d_in[5];
    const float* qk_b   = (const float*)d_in[6];
    const float* v_w    = (const float*)d_in[7];
    const float* v_b    = (const float*)d_in[8];
    const float* proj_w = (const float*)d_in[9];
    const float* proj_b = (const float*)d_in[10];
    const float* rpb    = (const float*)d_in[11];
    float* out = (float*)d_out;

    ln_stats_kernel<<<NPIX / 64, 256>>>(x);
    gemm1_kernel<<<dim3(GEMM1_N / 128, NPIX / 128), 256>>>(x, pre_g, pre_b, qk_w, qk_b, v_w, v_b);
    attn_kernel<<<dim3(NH, NWIN), 128>>>(rpb);
    ln2_gelu_kernel<<<NPIX, 256>>>(post_g, post_b);
    gemm2_kernel<<<dim3(GEMM2_N / 128, NPIX / 128), 256>>>(x, proj_w, proj_b, out);
}

// round 3
// speedup vs baseline: 1.4240x; 1.4240x over previous
#include <cuda_runtime.h>
#include <cuda_fp16.h>
#include <cstdint>
#include <math.h>

// ---------------- problem constants ----------------
#define B_IMG  32
#define C_IN   256
#define HWDIM  56
#define PIX_PER_IMG (HWDIM*HWDIM)      // 3136
#define NPIX   (B_IMG*PIX_PER_IMG)     // 100352
#define N_TOK  49
#define NH     8
#define DH     32
#define DE     1024
#define NWIN   (B_IMG*64)              // 2048
#define QSCALE 0.17677669529663687f

// ---------------- scratch ----------------
__device__ float g_mean[NPIX];
__device__ float g_rstd[NPIX];
__device__ float g_ln2m[NPIX];
__device__ float g_ln2r[NPIX];
__device__ float g_q[NWIN*NH*N_TOK*DH];        // [wi][head][n][d], q pre-scaled
__device__ float g_k[NWIN*NH*N_TOK*DH];        // [wi][head][n][d]
__device__ float g_v[(size_t)NPIX*DE];         // RASTER rows: [pixel][1024]

__device__ __forceinline__ float gelu_exact(float x) {
    return 0.5f * x * (1.0f + erff(x * 0.7071067811865476f));
}

// ---------------- mma helpers ----------------
__device__ __forceinline__ void mma16816(float* c, const uint32_t* a, const uint32_t* b) {
    asm volatile("mma.sync.aligned.m16n8k16.row.col.f32.f16.f16.f32 "
        "{%0,%1,%2,%3}, {%4,%5,%6,%7}, {%8,%9}, {%0,%1,%2,%3};"
        : "+f"(c[0]), "+f"(c[1]), "+f"(c[2]), "+f"(c[3])
        : "r"(a[0]), "r"(a[1]), "r"(a[2]), "r"(a[3]), "r"(b[0]), "r"(b[1]));
}
__device__ __forceinline__ uint32_t packh2(__half a, __half b) {
    __half2 t = __halves2half2(a, b);
    return *reinterpret_cast<uint32_t*>(&t);
}
__device__ __forceinline__ void splith(float v0, float v1, uint32_t& hi, uint32_t& lo) {
    __half h0 = __float2half_rn(v0), h1 = __float2half_rn(v1);
    __half l0 = __float2half_rn(v0 - __half2float(h0));
    __half l1 = __float2half_rn(v1 - __half2float(h1));
    hi = packh2(h0, h1); lo = packh2(l0, l1);
}

// smem fragment layouts (dynamic smem, 64KB):
//  As (uint4): [stage2][plane2][kt2][mt8][lane32]   -> 32KB
//  Bs (uint2): [stage2][plane2][kt2][nt16][lane32]  -> 32KB at +32768
#define AS_IDX(s,p,kt,mt)  (((((s)*2+(p))*2+(kt))*8+(mt))*32)
#define BS_IDX(s,p,kt,nt)  (((((s)*2+(p))*2+(kt))*16+(nt))*32)
#define SMEM_BYTES 65536

// ================= kernel 1: pre-LN stats =================
__global__ __launch_bounds__(256) void ln_stats_kernel(const float* __restrict__ x) {
    int pix0 = blockIdx.x * 64;
    int px = threadIdx.x & 63;
    int cg = threadIdx.x >> 6;
    int b  = pix0 / PIX_PER_IMG;
    int hw = pix0 % PIX_PER_IMG;
    const float* xb = x + (size_t)b * C_IN * PIX_PER_IMG + hw;
    float s = 0.f, ss = 0.f;
    for (int c = cg; c < C_IN; c += 4) {
        float v = xb[(size_t)c * PIX_PER_IMG + px];
        s += v; ss += v * v;
    }
    __shared__ float sh_s[4][64], sh_ss[4][64];
    sh_s[cg][px] = s; sh_ss[cg][px] = ss;
    __syncthreads();
    if (threadIdx.x < 64) {
        float t = 0.f, tt = 0.f;
        #pragma unroll
        for (int i = 0; i < 4; i++) { t += sh_s[i][threadIdx.x]; tt += sh_ss[i][threadIdx.x]; }
        float mean = t * (1.0f / 256.0f);
        float var  = tt * (1.0f / 256.0f) - mean * mean;
        g_mean[pix0 + threadIdx.x] = mean;
        g_rstd[pix0 + threadIdx.x] = rsqrtf(var + 1e-5f);
    }
}

// ================= GEMM1 (mma.sync fp16 x3): LN(x) @ [qk_w; v_w]^T =================
// M=NPIX, N=1536, K=256. BM=128, BN=128, BK=32, 8 warps, warp tile 32x64.
__global__ __launch_bounds__(256) void gemm1_mma(
    const float* __restrict__ x,
    const float* __restrict__ pre_g, const float* __restrict__ pre_b,
    const float* __restrict__ qk_w,  const float* __restrict__ qk_b,
    const float* __restrict__ v_w,   const float* __restrict__ v_b)
{
    extern __shared__ char smem[];
    uint4* As = (uint4*)smem;
    uint2* Bs = (uint2*)(smem + 32768);

    const int tid = threadIdx.x, lane = tid & 31, wid = tid >> 5;
    const int wm = wid >> 1, wn = wid & 1;
    const int mb = blockIdx.y * 128, nb = blockIdx.x * 128;

    // ---- A producer setup (this thread owns mt=wid, rows am0, am0+8) ----
    const int amt = wid;
    const int am0 = mb + amt * 16 + (lane >> 2);
    const int am1 = am0 + 8;
    int img0 = am0 / PIX_PER_IMG, hw0 = am0 - img0 * PIX_PER_IMG;
    int img1 = am1 / PIX_PER_IMG, hw1 = am1 - img1 * PIX_PER_IMG;
    const float* xr0 = x + (size_t)img0 * C_IN * PIX_PER_IMG + hw0;
    const float* xr1 = x + (size_t)img1 * C_IN * PIX_PER_IMG + hw1;
    const float mu0 = g_mean[am0], rs0 = g_rstd[am0];
    const float mu1 = g_mean[am1], rs1 = g_rstd[am1];
    const int acol = (lane & 3) * 2;

    // ---- B producer setup (this thread covers nt=wid and nt=wid+8) ----
    const int bo0 = nb + wid * 8 + (lane >> 2);
    const int bo1 = bo0 + 64;
    const float* bw0 = (bo0 < 512) ? (qk_w + (size_t)bo0 * 256) : (v_w + (size_t)(bo0 - 512) * 256);
    const float* bw1 = (bo1 < 512) ? (qk_w + (size_t)bo1 * 256) : (v_w + (size_t)(bo1 - 512) * 256);

    float acc[2][8][4];
    #pragma unroll
    for (int i = 0; i < 2; i++)
        #pragma unroll
        for (int j = 0; j < 8; j++)
            #pragma unroll
            for (int r = 0; r < 4; r++) acc[i][j][r] = 0.f;

    float  ar[16];
    float2 br[8];

#define G1_LOADA(KC) { \
    _Pragma("unroll") \
    for (int kt = 0; kt < 2; kt++) \
    _Pragma("unroll") \
    for (int p2 = 0; p2 < 2; p2++) { \
        int c = (KC) * 32 + kt * 16 + acol + 8 * p2; \
        int ib = (kt * 2 + p2) * 4; \
        ar[ib + 0] = xr0[(size_t)c * PIX_PER_IMG]; \
        ar[ib + 1] = xr0[(size_t)(c + 1) * PIX_PER_IMG]; \
        ar[ib + 2] = xr1[(size_t)c * PIX_PER_IMG]; \
        ar[ib + 3] = xr1[(size_t)(c + 1) * PIX_PER_IMG]; \
    } }

#define G1_LOADB(KC) { \
    _Pragma("unroll") \
    for (int nc = 0; nc < 2; nc++) { \
        const float* wsrc = nc ? bw1 : bw0; \
        _Pragma("unroll") \
        for (int kt = 0; kt < 2; kt++) \
        _Pragma("unroll") \
        for (int i = 0; i < 2; i++) \
            br[(nc * 2 + kt) * 2 + i] = *(const float2*)(wsrc + (KC) * 32 + kt * 16 + acol + 8 * i); \
    } }

#define G1_STORE(ST, KC) { \
    _Pragma("unroll") \
    for (int kt = 0; kt < 2; kt++) { \
        uint4 hi, lo; \
        _Pragma("unroll") \
        for (int p2 = 0; p2 < 2; p2++) { \
            int c = (KC) * 32 + kt * 16 + acol + 8 * p2; \
            float gg0 = pre_g[c], bb0 = pre_b[c], gg1 = pre_g[c + 1], bb1 = pre_b[c + 1]; \
            int ib = (kt * 2 + p2) * 4; \
            float t00 = (ar[ib + 0] - mu0) * rs0 * gg0 + bb0; \
            float t01 = (ar[ib + 1] - mu0) * rs0 * gg1 + bb1; \
            float t10 = (ar[ib + 2] - mu1) * rs1 * gg0 + bb0; \
            float t11 = (ar[ib + 3] - mu1) * rs1 * gg1 + bb1; \
            uint32_t h0, l0, h1, l1; \
            splith(t00, t01, h0, l0); splith(t10, t11, h1, l1); \
            (&hi.x)[2 * p2 + 0] = h0; (&hi.x)[2 * p2 + 1] = h1; \
            (&lo.x)[2 * p2 + 0] = l0; (&lo.x)[2 * p2 + 1] = l1; \
        } \
        As[AS_IDX(ST, 0, kt, amt) + lane] = hi; \
        As[AS_IDX(ST, 1, kt, amt) + lane] = lo; \
    } \
    _Pragma("unroll") \
    for (int nc = 0; nc < 2; nc++) { \
        int nt = wid + nc * 8; \
        _Pragma("unroll") \
        for (int kt = 0; kt < 2; kt++) { \
            uint2 hi, lo; \
            _Pragma("unroll") \
            for (int i = 0; i < 2; i++) { \
                float2 f = br[(nc * 2 + kt) * 2 + i]; \
                uint32_t h, l; splith(f.x, f.y, h, l); \
                (&hi.x)[i] = h; (&lo.x)[i] = l; \
            } \
            Bs[BS_IDX(ST, 0, kt, nt) + lane] = hi; \
            Bs[BS_IDX(ST, 1, kt, nt) + lane] = lo; \
        } \
    } }

    G1_LOADA(0); G1_LOADB(0); G1_STORE(0, 0);
    __syncthreads();

    const int NCH = 8;
    for (int kc = 0; kc < NCH; kc++) {
        int buf = kc & 1;
        if (kc + 1 < NCH) { G1_LOADA(kc + 1); G1_LOADB(kc + 1); }
        #pragma unroll
        for (int kt = 0; kt < 2; kt++) {
            uint32_t ah[2][4], al[2][4], bh[8][2], bl[8][2];
            #pragma unroll
            for (int mti = 0; mti < 2; mti++) {
                *(uint4*)ah[mti] = As[AS_IDX(buf, 0, kt, wm * 2 + mti) + lane];
                *(uint4*)al[mti] = As[AS_IDX(buf, 1, kt, wm * 2 + mti) + lane];
            }
            #pragma unroll
            for (int nti = 0; nti < 8; nti++) {
                *(uint2*)bh[nti] = Bs[BS_IDX(buf, 0, kt, wn * 8 + nti) + lane];
                *(uint2*)bl[nti] = Bs[BS_IDX(buf, 1, kt, wn * 8 + nti) + lane];
            }
            #pragma unroll
            for (int mti = 0; mti < 2; mti++)
                #pragma unroll
                for (int nti = 0; nti < 8; nti++) {
                    mma16816(acc[mti][nti], ah[mti], bh[nti]);
                    mma16816(acc[mti][nti], al[mti], bh[nti]);
                    mma16816(acc[mti][nti], ah[mti], bl[nti]);
                }
        }
        if (kc + 1 < NCH) { G1_STORE(buf ^ 1, kc + 1); }
        __syncthreads();
    }

    // ---- epilogue: stage 64-col halves in smem, scatter q/k/v coalesced ----
    float* stg = (float*)smem;
    for (int h = 0; h < 2; h++) {
        if (wn == h) {
            #pragma unroll
            for (int mti = 0; mti < 2; mti++)
                #pragma unroll
                for (int nti = 0; nti < 8; nti++) {
                    int r0 = wm * 32 + mti * 16 + (lane >> 2);
                    int c0 = nti * 8 + (lane & 3) * 2;
                    stg[r0 * 65 + c0]       = acc[mti][nti][0];
                    stg[r0 * 65 + c0 + 1]   = acc[mti][nti][1];
                    stg[(r0 + 8) * 65 + c0]     = acc[mti][nti][2];
                    stg[(r0 + 8) * 65 + c0 + 1] = acc[mti][nti][3];
                }
        }
        __syncthreads();
        int cc = tid & 63, qr = tid >> 6;
        int o = nb + h * 64 + cc;
        float bias = (o < 512) ? qk_b[o] : v_b[o - 512];
        #pragma unroll 4
        for (int i = 0; i < 32; i++) {
            int ml = qr + i * 4;
            float val = stg[ml * 65 + cc] + bias;
            int m = mb + ml;
            if (o < 512) {
                int bimg = m / PIX_PER_IMG;
                int hw = m - bimg * PIX_PER_IMG;
                int hh = hw / HWDIM, ww = hw - hh * HWDIM;
                int wi = bimg * 64 + (hh & 7) * 8 + (ww & 7);
                int n  = (hh >> 3) * 7 + (ww >> 3);
                if (o < 256)
                    g_q[(((size_t)wi * 8 + (o >> 5)) * 49 + n) * 32 + (o & 31)] = val * QSCALE;
                else {
                    int q2 = o - 256;
                    g_k[(((size_t)wi * 8 + (q2 >> 5)) * 49 + n) * 32 + (q2 & 31)] = val;
                }
            } else {
                g_v[(size_t)m * DE + (o - 512)] = val;
            }
        }
        __syncthreads();
    }
#undef G1_LOADA
#undef G1_LOADB
#undef G1_STORE
}

// ================= attention: one CTA per (window, head) =================
__global__ __launch_bounds__(128) void attn_kernel(const float* __restrict__ rpb) {
    int head = blockIdx.x;
    int wi   = blockIdx.y;
    int wp   = wi & 63;
    int bimg = wi >> 6;
    int tid  = threadIdx.x;

    __shared__ float Qs[49][33];
    __shared__ float Ks[49][33];
    __shared__ float Vs[49][64];
    __shared__ float Ss[49 * 49];
    __shared__ float rpbs[169];

    const float* qbase = g_q + ((size_t)wi * 8 + head) * 49 * 32;
    const float* kbase = g_k + ((size_t)wi * 8 + head) * 49 * 32;

    for (int i = tid; i < 49 * 32; i += 128) {
        Qs[i >> 5][i & 31] = qbase[i];
        Ks[i >> 5][i & 31] = kbase[i];
    }
    for (int i = tid; i < 169; i += 128)
        rpbs[i] = rpb[((size_t)wp * 169 + i) * 8 + head];
    for (int i = tid; i < 49 * 64; i += 128) {
        int n = i >> 6, vh = i & 63;
        int hh = (n / 7) * 8 + (wp >> 3), ww = (n % 7) * 8 + (wp & 7);
        size_t pix = (size_t)bimg * PIX_PER_IMG + hh * HWDIM + ww;
        Vs[n][vh] = g_v[pix * DE + head * 64 + vh];
    }
    __syncthreads();

    for (int i = tid; i < 49 * 49; i += 128) {
        int n = i / 49, m = i % 49;
        float s = 0.f;
        #pragma unroll
        for (int d = 0; d < 32; d++) s += Qs[n][d] * Ks[m][d];
        int i1 = n / 7, j1 = n % 7, i2 = m / 7, j2 = m % 7;
        s += rpbs[(i1 - i2 + 6) * 13 + (j1 - j2 + 6)];
        Ss[i] = s;
    }
    __syncthreads();

    if (tid < 49) {
        float* row = Ss + tid * 49;
        float mx = -1e30f;
        #pragma unroll 7
        for (int m = 0; m < 49; m++) mx = fmaxf(mx, row[m]);
        float sum = 0.f;
        #pragma unroll 7
        for (int m = 0; m < 49; m++) { float e = __expf(row[m] - mx); row[m] = e; sum += e; }
        float inv = 1.0f / sum;
        #pragma unroll 7
        for (int m = 0; m < 49; m++) row[m] *= inv;
    }
    __syncthreads();

    for (int i = tid; i < 49 * 64; i += 128) {
        int n = i >> 6, vh = i & 63;
        float o = 0.f;
        #pragma unroll 7
        for (int m = 0; m < 49; m++) o += Ss[n * 49 + m] * Vs[m][vh];
        int hh = (n / 7) * 8 + (wp >> 3), ww = (n % 7) * 8 + (wp & 7);
        size_t pix = (size_t)bimg * PIX_PER_IMG + hh * HWDIM + ww;
        g_v[pix * DE + head * 64 + vh] = o;
    }
}

// ================= post-LN stats over first 512 cols of g_v (per pixel-row) =================
__global__ __launch_bounds__(256) void ln2_stats_kernel() {
    int row = blockIdx.x * 8 + (threadIdx.x >> 5);
    int lane = threadIdx.x & 31;
    const float4* p = (const float4*)(g_v + (size_t)row * DE);
    float s = 0.f, ss = 0.f;
    #pragma unroll
    for (int j = 0; j < 4; j++) {
        float4 v = p[lane + 32 * j];
        s  += v.x + v.y + v.z + v.w;
        ss += v.x * v.x + v.y * v.y + v.z * v.z + v.w * v.w;
    }
    #pragma unroll
    for (int off = 16; off; off >>= 1) {
        s  += __shfl_down_sync(0xffffffffu, s, off);
        ss += __shfl_down_sync(0xffffffffu, ss, off);
    }
    if (lane == 0) {
        float mean = s * (1.0f / 512.0f);
        float var  = ss * (1.0f / 512.0f) - mean * mean;
        g_ln2m[row] = mean;
        g_ln2r[row] = rsqrtf(var + 1e-5f);
    }
}

// ================= GEMM2 (mma.sync fp16 x3): gelu(LN/id(g_v)) @ proj_w^T + bias + residual + roll =================
// M=NPIX, N=256, K=1024. BM=128, BN=128, BK=32. LN+GELU fused into A-converter.
__global__ __launch_bounds__(256) void gemm2_mma(
    const float* __restrict__ x,
    const float* __restrict__ post_g, const float* __restrict__ post_b,
    const float* __restrict__ proj_w, const float* __restrict__ proj_b,
    float* __restrict__ out)
{
    extern __shared__ char smem[];
    uint4* As = (uint4*)smem;
    uint2* Bs = (uint2*)(smem + 32768);

    const int tid = threadIdx.x, lane = tid & 31, wid = tid >> 5;
    const int wm = wid >> 1, wn = wid & 1;
    const int mb = blockIdx.x * 128, nb = blockIdx.y * 128;

    const int amt = wid;
    const int am0 = mb + amt * 16 + (lane >> 2);
    const int am1 = am0 + 8;
    const float* gv0 = g_v + (size_t)am0 * DE;
    const float* gv1 = g_v + (size_t)am1 * DE;
    const float mu0 = g_ln2m[am0], rs0 = g_ln2r[am0];
    const float mu1 = g_ln2m[am1], rs1 = g_ln2r[am1];
    const int acol = (lane & 3) * 2;

    const int bo0 = nb + wid * 8 + (lane >> 2);
    const int bo1 = bo0 + 64;
    const float* bw0 = proj_w + (size_t)bo0 * 1024;
    const float* bw1 = proj_w + (size_t)bo1 * 1024;

    float acc[2][8][4];
    #pragma unroll
    for (int i = 0; i < 2; i++)
        #pragma unroll
        for (int j = 0; j < 8; j++)
            #pragma unroll
            for (int r = 0; r < 4; r++) acc[i][j][r] = 0.f;

    float2 a2r[8];
    float2 br[8];

#define G2_LOADA(KC) { \
    _Pragma("unroll") \
    for (int kt = 0; kt < 2; kt++) \
    _Pragma("unroll") \
    for (int p2 = 0; p2 < 2; p2++) { \
        int c = (KC) * 32 + kt * 16 + acol + 8 * p2; \
        a2r[(kt * 2 + p2) * 2 + 0] = *(const float2*)(gv0 + c); \
        a2r[(kt * 2 + p2) * 2 + 1] = *(const float2*)(gv1 + c); \
    } }

#define G2_LOADB(KC) { \
    _Pragma("unroll") \
    for (int nc = 0; nc < 2; nc++) { \
        const float* wsrc = nc ? bw1 : bw0; \
        _Pragma("unroll") \
        for (int kt = 0; kt < 2; kt++) \
        _Pragma("unroll") \
        for (int i = 0; i < 2; i++) \
            br[(nc * 2 + kt) * 2 + i] = *(const float2*)(wsrc + (KC) * 32 + kt * 16 + acol + 8 * i); \
    } }

#define G2_STORE(ST, KC) { \
    _Pragma("unroll") \
    for (int kt = 0; kt < 2; kt++) { \
        uint4 hi, lo; \
        _Pragma("unroll") \
        for (int p2 = 0; p2 < 2; p2++) { \
            int c = (KC) * 32 + kt * 16 + acol + 8 * p2; \
            float2 f0 = a2r[(kt * 2 + p2) * 2 + 0]; \
            float2 f1 = a2r[(kt * 2 + p2) * 2 + 1]; \
            float t00 = f0.x, t01 = f0.y, t10 = f1.x, t11 = f1.y; \
            if (c < 512) { \
                float gg0 = post_g[c], bb0 = post_b[c]; \
                float gg1 = post_g[c + 1], bb1 = post_b[c + 1]; \
                t00 = (t00 - mu0) * rs0 * gg0 + bb0; \
                t01 = (t01 - mu0) * rs0 * gg1 + bb1; \
                t10 = (t10 - mu1) * rs1 * gg0 + bb0; \
                t11 = (t11 - mu1) * rs1 * gg1 + bb1; \
            } \
            t00 = gelu_exact(t00); t01 = gelu_exact(t01); \
            t10 = gelu_exact(t10); t11 = gelu_exact(t11); \
            uint32_t h0, l0, h1, l1; \
            splith(t00, t01, h0, l0); splith(t10, t11, h1, l1); \
            (&hi.x)[2 * p2 + 0] = h0; (&hi.x)[2 * p2 + 1] = h1; \
            (&lo.x)[2 * p2 + 0] = l0; (&lo.x)[2 * p2 + 1] = l1; \
        } \
        As[AS_IDX(ST, 0, kt, amt) + lane] = hi; \
        As[AS_IDX(ST, 1, kt, amt) + lane] = lo; \
    } \
    _Pragma("unroll") \
    for (int nc = 0; nc < 2; nc++) { \
        int nt = wid + nc * 8; \
        _Pragma("unroll") \
        for (int kt = 0; kt < 2; kt++) { \
            uint2 hi, lo; \
            _Pragma("unroll") \
            for (int i = 0; i < 2; i++) { \
                float2 f = br[(nc * 2 + kt) * 2 + i]; \
                uint32_t h, l; splith(f.x, f.y, h, l); \
                (&hi.x)[i] = h; (&lo.x)[i] = l; \
            } \
            Bs[BS_IDX(ST, 0, kt, nt) + lane] = hi; \
            Bs[BS_IDX(ST, 1, kt, nt) + lane] = lo; \
        } \
    } }

    G2_LOADA(0); G2_LOADB(0); G2_STORE(0, 0);
    __syncthreads();

    const int NCH = 32;
    for (int kc = 0; kc < NCH; kc++) {
        int buf = kc & 1;
        if (kc + 1 < NCH) { G2_LOADA(kc + 1); G2_LOADB(kc + 1); }
        #pragma unroll
        for (int kt = 0; kt < 2; kt++) {
            uint32_t ah[2][4], al[2][4], bh[8][2], bl[8][2];
            #pragma unroll
            for (int mti = 0; mti < 2; mti++) {
                *(uint4*)ah[mti] = As[AS_IDX(buf, 0, kt, wm * 2 + mti) + lane];
                *(uint4*)al[mti] = As[AS_IDX(buf, 1, kt, wm * 2 + mti) + lane];
            }
            #pragma unroll
            for (int nti = 0; nti < 8; nti++) {
                *(uint2*)bh[nti] = Bs[BS_IDX(buf, 0, kt, wn * 8 + nti) + lane];
                *(uint2*)bl[nti] = Bs[BS_IDX(buf, 1, kt, wn * 8 + nti) + lane];
            }
            #pragma unroll
            for (int mti = 0; mti < 2; mti++)
                #pragma unroll
                for (int nti = 0; nti < 8; nti++) {
                    mma16816(acc[mti][nti], ah[mti], bh[nti]);
                    mma16816(acc[mti][nti], al[mti], bh[nti]);
                    mma16816(acc[mti][nti], ah[mti], bl[nti]);
                }
        }
        if (kc + 1 < NCH) { G2_STORE(buf ^ 1, kc + 1); }
        __syncthreads();
    }

    // ---- epilogue: stage halves, +bias +residual, rolled coalesced writes ----
    float* stg = (float*)smem;
    const int ml = tid & 127;
    const int chalf = tid >> 7;
    {
        int m = mb + ml;
        int bimg = m / PIX_PER_IMG;
        int hw = m - bimg * PIX_PER_IMG;
        int hh = hw / HWDIM, ww = hw - hh * HWDIM;
        int h2 = hh + 2; if (h2 >= HWDIM) h2 -= HWDIM;
        int w2 = ww + 2; if (w2 >= HWDIM) w2 -= HWDIM;
        size_t inbase  = (size_t)bimg * C_IN * PIX_PER_IMG + hw;
        size_t outbase = (size_t)bimg * C_IN * PIX_PER_IMG + h2 * HWDIM + w2;

        for (int h = 0; h < 2; h++) {
            if (wn == h) {
                #pragma unroll
                for (int mti = 0; mti < 2; mti++)
                    #pragma unroll
                    for (int nti = 0; nti < 8; nti++) {
                        int r0 = wm * 32 + mti * 16 + (lane >> 2);
                        int c0 = nti * 8 + (lane & 3) * 2;
                        stg[r0 * 65 + c0]       = acc[mti][nti][0];
                        stg[r0 * 65 + c0 + 1]   = acc[mti][nti][1];
                        stg[(r0 + 8) * 65 + c0]     = acc[mti][nti][2];
                        stg[(r0 + 8) * 65 + c0 + 1] = acc[mti][nti][3];
                    }
            }
            __syncthreads();
            #pragma unroll 8
            for (int i = 0; i < 32; i++) {
                int c = i * 2 + chalf;
                int o = nb + h * 64 + c;
                float val = stg[ml * 65 + c] + proj_b[o] + x[inbase + (size_t)o * PIX_PER_IMG];
                out[outbase + (size_t)o * PIX_PER_IMG] = val;
            }
            __syncthreads();
        }
    }
#undef G2_LOADA
#undef G2_LOADB
#undef G2_STORE
}

// ================= launch =================
extern "C" void kernel_launch(void* const* d_in, const int* in_sizes, int n_in,
                              void* d_out, int out_size) {
    const float* x      = (const float*)d_in[0];
    const float* pre_g  = (const float*)d_in[1];
    const float* pre_b  = (const float*)d_in[2];
    const float* post_g = (const float*)d_in[3];
    const float* post_b = (const float*)d_in[4];
    const float* qk_w   = (const float*)d_in[5];
    const float* qk_b   = (const float*)d_in[6];
    const float* v_w    = (const float*)d_in[7];
    const float* v_b    = (const float*)d_in[8];
    const float* proj_w = (const float*)d_in[9];
    const float* proj_b = (const float*)d_in[10];
    const float* rpb    = (const float*)d_in[11];
    float* out = (float*)d_out;

    static int configured = 0;
    if (!configured) {
        cudaFuncSetAttribute(gemm1_mma, cudaFuncAttributeMaxDynamicSharedMemorySize, SMEM_BYTES);
        cudaFuncSetAttribute(gemm2_mma, cudaFuncAttributeMaxDynamicSharedMemorySize, SMEM_BYTES);
        configured = 1;
    }

    ln_stats_kernel<<<NPIX / 64, 256>>>(x);
    gemm1_mma<<<dim3(12, NPIX / 128), 256, SMEM_BYTES>>>(x, pre_g, pre_b, qk_w, qk_b, v_w, v_b);
    attn_kernel<<<dim3(NH, NWIN), 128>>>(rpb);
    ln2_stats_kernel<<<NPIX / 8, 256>>>();
    gemm2_mma<<<dim3(NPIX / 128, 2), 256, SMEM_BYTES>>>(x, post_g, post_b, proj_w, proj_b, out);
}

// round 4
// speedup vs baseline: 1.8998x; 1.3341x over previous
#include <cuda_runtime.h>
#include <cuda_fp16.h>
#include <cstdint>
#include <math.h>

// ---------------- problem constants ----------------
#define B_IMG  32
#define C_IN   256
#define HWDIM  56
#define PIX_PER_IMG (HWDIM*HWDIM)      // 3136
#define NPIX   (B_IMG*PIX_PER_IMG)     // 100352
#define N_TOK  49
#define NH     8
#define DH     32
#define DE     1024
#define NWIN   (B_IMG*64)              // 2048
#define QSCALE 0.17677669529663687f
#define MT_TOT (NPIX/16)               // 6272

// ---------------- scratch ----------------
__device__ float g_mean[NPIX];
__device__ float g_rstd[NPIX];
__device__ float g_ln2m[NPIX];
__device__ float g_ln2r[NPIX];
__device__ float g_q[NWIN*NH*N_TOK*DH];
__device__ float g_k[NWIN*NH*N_TOK*DH];
__device__ float g_v[(size_t)NPIX*DE];         // RASTER rows: [pixel][1024]

// fragment-layout fp16 hi/lo buffers
__device__ uint4 g_a1h[(size_t)MT_TOT*16*32];  // [mt][kt16][lane]
__device__ uint4 g_a1l[(size_t)MT_TOT*16*32];
__device__ uint2 g_b1h[192*16*32];             // [nt][kt16][lane]
__device__ uint2 g_b1l[192*16*32];
__device__ uint4 g_a2h[(size_t)MT_TOT*64*32];  // [mt][kt64][lane]
__device__ uint4 g_a2l[(size_t)MT_TOT*64*32];
__device__ uint2 g_b2h[32*64*32];              // [nt][kt64][lane]
__device__ uint2 g_b2l[32*64*32];

__device__ __forceinline__ float gelu_exact(float x) {
    return 0.5f * x * (1.0f + erff(x * 0.7071067811865476f));
}

// ---------------- mma helpers ----------------
__device__ __forceinline__ void mma16816(float* c, const uint32_t* a, const uint32_t* b) {
    asm volatile("mma.sync.aligned.m16n8k16.row.col.f32.f16.f16.f32 "
        "{%0,%1,%2,%3}, {%4,%5,%6,%7}, {%8,%9}, {%0,%1,%2,%3};"
        : "+f"(c[0]), "+f"(c[1]), "+f"(c[2]), "+f"(c[3])
        : "r"(a[0]), "r"(a[1]), "r"(a[2]), "r"(a[3]), "r"(b[0]), "r"(b[1]));
}
__device__ __forceinline__ uint32_t packh2(__half a, __half b) {
    __half2 t = __halves2half2(a, b);
    return *reinterpret_cast<uint32_t*>(&t);
}
__device__ __forceinline__ void splith(float v0, float v1, uint32_t& hi, uint32_t& lo) {
    __half h0 = __float2half_rn(v0), h1 = __float2half_rn(v1);
    __half l0 = __float2half_rn(v0 - __half2float(h0));
    __half l1 = __float2half_rn(v1 - __half2float(h1));
    hi = packh2(h0, h1); lo = packh2(l0, l1);
}

// smem fragment layouts (dynamic smem, 64KB):
//  As (uint4): [stage2][plane2][kt2][mt8][lane32]   -> 32KB
//  Bs (uint2): [stage2][plane2][kt2][nt16][lane32]  -> 32KB at +32768
#define AS_IDX(s,p,kt,mt)  (((((s)*2+(p))*2+(kt))*8+(mt))*32)
#define BS_IDX(s,p,kt,nt)  (((((s)*2+(p))*2+(kt))*16+(nt))*32)
#define SMEM_BYTES 65536

// ================= kernel: pre-LN stats =================
__global__ __launch_bounds__(256) void ln_stats_kernel(const float* __restrict__ x) {
    int pix0 = blockIdx.x * 64;
    int px = threadIdx.x & 63;
    int cg = threadIdx.x >> 6;
    int b  = pix0 / PIX_PER_IMG;
    int hw = pix0 % PIX_PER_IMG;
    const float* xb = x + (size_t)b * C_IN * PIX_PER_IMG + hw;
    float s = 0.f, ss = 0.f;
    for (int c = cg; c < C_IN; c += 4) {
        float v = xb[(size_t)c * PIX_PER_IMG + px];
        s += v; ss += v * v;
    }
    __shared__ float sh_s[4][64], sh_ss[4][64];
    sh_s[cg][px] = s; sh_ss[cg][px] = ss;
    __syncthreads();
    if (threadIdx.x < 64) {
        float t = 0.f, tt = 0.f;
        #pragma unroll
        for (int i = 0; i < 4; i++) { t += sh_s[i][threadIdx.x]; tt += sh_ss[i][threadIdx.x]; }
        float mean = t * (1.0f / 256.0f);
        float var  = tt * (1.0f / 256.0f) - mean * mean;
        g_mean[pix0 + threadIdx.x] = mean;
        g_rstd[pix0 + threadIdx.x] = rsqrtf(var + 1e-5f);
    }
}

// ================= converters =================
// weights for GEMM1: [qk_w;v_w] rows 0..1535, K=256 -> B frags
__global__ __launch_bounds__(256) void conv_w1(const float* __restrict__ qk_w,
                                               const float* __restrict__ v_w) {
    int t = blockIdx.x * 256 + threadIdx.x;     // 0..98303
    int lane = t & 31;
    int kt = (t >> 5) & 15;
    int nt = t >> 9;
    int n = nt * 8 + (lane >> 2);
    int k = kt * 16 + (lane & 3) * 2;
    const float* wr = (n < 512) ? qk_w + (size_t)n * 256 : v_w + (size_t)(n - 512) * 256;
    float2 f0 = *(const float2*)(wr + k);
    float2 f1 = *(const float2*)(wr + k + 8);
    uint2 hi, lo;
    splith(f0.x, f0.y, hi.x, lo.x);
    splith(f1.x, f1.y, hi.y, lo.y);
    g_b1h[t] = hi; g_b1l[t] = lo;
}

// proj_w 256x1024 -> B frags
__global__ __launch_bounds__(256) void conv_w2(const float* __restrict__ proj_w) {
    int t = blockIdx.x * 256 + threadIdx.x;     // 0..65535
    int lane = t & 31;
    int kt = (t >> 5) & 63;
    int nt = t >> 11;
    int n = nt * 8 + (lane >> 2);
    int k = kt * 16 + (lane & 3) * 2;
    const float* wr = proj_w + (size_t)n * 1024;
    float2 f0 = *(const float2*)(wr + k);
    float2 f1 = *(const float2*)(wr + k + 8);
    uint2 hi, lo;
    splith(f0.x, f0.y, hi.x, lo.x);
    splith(f1.x, f1.y, hi.y, lo.y);
    g_b2h[t] = hi; g_b2l[t] = lo;
}

// LN(x) -> A frags for GEMM1 (one block per mtile)
__global__ __launch_bounds__(256) void conv_a1(const float* __restrict__ x,
                                               const float* __restrict__ pre_g,
                                               const float* __restrict__ pre_b) {
    int mt = blockIdx.x;
    int w = threadIdx.x >> 5, lane = threadIdx.x & 31;
    int r0 = mt * 16 + (lane >> 2), r1 = r0 + 8;
    int img = r0 / PIX_PER_IMG;
    int hw0 = r0 - img * PIX_PER_IMG;
    int hw1 = hw0 + 8;
    const float* xb = x + (size_t)img * C_IN * PIX_PER_IMG;
    float mu0 = g_mean[r0], rs0 = g_rstd[r0];
    float mu1 = g_mean[r1], rs1 = g_rstd[r1];
    #pragma unroll
    for (int kk = 0; kk < 2; kk++) {
        int kt = w + kk * 8;
        int c = kt * 16 + (lane & 3) * 2;
        uint4 hi, lo;
        #pragma unroll
        for (int p2 = 0; p2 < 2; p2++) {
            int cc = c + p2 * 8;
            float g0 = pre_g[cc], b0 = pre_b[cc], g1 = pre_g[cc + 1], b1 = pre_b[cc + 1];
            float t00 = (xb[(size_t)cc * PIX_PER_IMG + hw0] - mu0) * rs0 * g0 + b0;
            float t01 = (xb[(size_t)(cc + 1) * PIX_PER_IMG + hw0] - mu0) * rs0 * g1 + b1;
            float t10 = (xb[(size_t)cc * PIX_PER_IMG + hw1] - mu1) * rs1 * g0 + b0;
            float t11 = (xb[(size_t)(cc + 1) * PIX_PER_IMG + hw1] - mu1) * rs1 * g1 + b1;
            splith(t00, t01, (&hi.x)[2 * p2], (&lo.x)[2 * p2]);
            splith(t10, t11, (&hi.x)[2 * p2 + 1], (&lo.x)[2 * p2 + 1]);
        }
        size_t idx = ((size_t)mt * 16 + kt) * 32 + lane;
        g_a1h[idx] = hi; g_a1l[idx] = lo;
    }
}

// gelu(postLN/id(g_v)) -> A frags for GEMM2 (one block per mtile)
__global__ __launch_bounds__(256) void conv_a2(const float* __restrict__ post_g,
                                               const float* __restrict__ post_b) {
    int mt = blockIdx.x;
    int w = threadIdx.x >> 5, lane = threadIdx.x & 31;
    int r0 = mt * 16 + (lane >> 2), r1 = r0 + 8;
    const float* gv0 = g_v + (size_t)r0 * DE;
    const float* gv1 = g_v + (size_t)r1 * DE;
    float mu0 = g_ln2m[r0], rs0 = g_ln2r[r0];
    float mu1 = g_ln2m[r1], rs1 = g_ln2r[r1];
    #pragma unroll
    for (int kk = 0; kk < 8; kk++) {
        int kt = w + kk * 8;
        int c = kt * 16 + (lane & 3) * 2;
        uint4 hi, lo;
        #pragma unroll
        for (int p2 = 0; p2 < 2; p2++) {
            int cc = c + p2 * 8;
            float2 f0 = *(const float2*)(gv0 + cc);
            float2 f1 = *(const float2*)(gv1 + cc);
            float t00 = f0.x, t01 = f0.y, t10 = f1.x, t11 = f1.y;
            if (cc < 512) {
                float g0 = post_g[cc], b0 = post_b[cc];
                float g1 = post_g[cc + 1], b1 = post_b[cc + 1];
                t00 = (t00 - mu0) * rs0 * g0 + b0;
                t01 = (t01 - mu0) * rs0 * g1 + b1;
                t10 = (t10 - mu1) * rs1 * g0 + b0;
                t11 = (t11 - mu1) * rs1 * g1 + b1;
            }
            t00 = gelu_exact(t00); t01 = gelu_exact(t01);
            t10 = gelu_exact(t10); t11 = gelu_exact(t11);
            splith(t00, t01, (&hi.x)[2 * p2], (&lo.x)[2 * p2]);
            splith(t10, t11, (&hi.x)[2 * p2 + 1], (&lo.x)[2 * p2 + 1]);
        }
        size_t idx = ((size_t)mt * 64 + kt) * 32 + lane;
        g_a2h[idx] = hi; g_a2l[idx] = lo;
    }
}

// ================= GEMM1 (mma.sync fp16 x3): pre-converted frags =================
// M=NPIX, N=1536, K=256. BM=128, BN=128, BK=32 (2 kts/stage), 8 warps.
__global__ __launch_bounds__(256) void gemm1_mma(
    const float* __restrict__ qk_b, const float* __restrict__ v_b)
{
    extern __shared__ char smem[];
    uint4* As = (uint4*)smem;
    uint2* Bs = (uint2*)(smem + 32768);

    const int tid = threadIdx.x, lane = tid & 31, wid = tid >> 5;
    const int wm = wid >> 1, wn = wid & 1;
    const int mb = blockIdx.y * 128, nb = blockIdx.x * 128;
    const int mtg0 = mb >> 4, ntg0 = nb >> 3;

    float acc[2][8][4];
    #pragma unroll
    for (int i = 0; i < 2; i++)
        #pragma unroll
        for (int j = 0; j < 8; j++)
            #pragma unroll
            for (int r = 0; r < 4; r++) acc[i][j][r] = 0.f;

    // producer decomposition (per thread: 4 A uint4, 8 B uint2)
    int a_lane[4], a_mt[4], a_ktl[4], a_p[4];
    #pragma unroll
    for (int j = 0; j < 4; j++) {
        int i = tid + j * 256;
        a_lane[j] = i & 31; a_mt[j] = (i >> 5) & 7; a_ktl[j] = (i >> 8) & 1; a_p[j] = i >> 9;
    }
    int b_lane[8], b_nt[8], b_ktl[8], b_p[8];
    #pragma unroll
    for (int j = 0; j < 8; j++) {
        int i = tid + j * 256;
        b_lane[j] = i & 31; b_nt[j] = (i >> 5) & 15; b_ktl[j] = (i >> 9) & 1; b_p[j] = i >> 10;
    }

#define G1_COPY(ST, KC) { \
    _Pragma("unroll") \
    for (int j = 0; j < 4; j++) { \
        const uint4* src = a_p[j] ? g_a1l : g_a1h; \
        As[AS_IDX(ST, a_p[j], a_ktl[j], a_mt[j]) + a_lane[j]] = \
            src[((size_t)(mtg0 + a_mt[j]) * 16 + (KC) * 2 + a_ktl[j]) * 32 + a_lane[j]]; \
    } \
    _Pragma("unroll") \
    for (int j = 0; j < 8; j++) { \
        const uint2* src = b_p[j] ? g_b1l : g_b1h; \
        Bs[BS_IDX(ST, b_p[j], b_ktl[j], b_nt[j]) + b_lane[j]] = \
            src[((size_t)(ntg0 + b_nt[j]) * 16 + (KC) * 2 + b_ktl[j]) * 32 + b_lane[j]]; \
    } }

    G1_COPY(0, 0);
    __syncthreads();

    const int NCH = 8;
    for (int kc = 0; kc < NCH; kc++) {
        int buf = kc & 1;
        if (kc + 1 < NCH) { G1_COPY(buf ^ 1, kc + 1); }
        #pragma unroll
        for (int kt = 0; kt < 2; kt++) {
            uint32_t ah[2][4], al[2][4], bh[8][2], bl[8][2];
            #pragma unroll
            for (int mti = 0; mti < 2; mti++) {
                *(uint4*)ah[mti] = As[AS_IDX(buf, 0, kt, wm * 2 + mti) + lane];
                *(uint4*)al[mti] = As[AS_IDX(buf, 1, kt, wm * 2 + mti) + lane];
            }
            #pragma unroll
            for (int nti = 0; nti < 8; nti++) {
                *(uint2*)bh[nti] = Bs[BS_IDX(buf, 0, kt, wn * 8 + nti) + lane];
                *(uint2*)bl[nti] = Bs[BS_IDX(buf, 1, kt, wn * 8 + nti) + lane];
            }
            #pragma unroll
            for (int mti = 0; mti < 2; mti++)
                #pragma unroll
                for (int nti = 0; nti < 8; nti++) {
                    mma16816(acc[mti][nti], ah[mti], bh[nti]);
                    mma16816(acc[mti][nti], al[mti], bh[nti]);
                    mma16816(acc[mti][nti], ah[mti], bl[nti]);
                }
        }
        __syncthreads();
    }

    // ---- epilogue: stage 64-col halves, scatter q/k/v ----
    float* stg = (float*)smem;
    for (int h = 0; h < 2; h++) {
        if (wn == h) {
            #pragma unroll
            for (int mti = 0; mti < 2; mti++)
                #pragma unroll
                for (int nti = 0; nti < 8; nti++) {
                    int r0 = wm * 32 + mti * 16 + (lane >> 2);
                    int c0 = nti * 8 + (lane & 3) * 2;
                    stg[r0 * 65 + c0]       = acc[mti][nti][0];
                    stg[r0 * 65 + c0 + 1]   = acc[mti][nti][1];
                    stg[(r0 + 8) * 65 + c0]     = acc[mti][nti][2];
                    stg[(r0 + 8) * 65 + c0 + 1] = acc[mti][nti][3];
                }
        }
        __syncthreads();
        int cc = tid & 63, qr = tid >> 6;
        int o = nb + h * 64 + cc;
        float bias = (o < 512) ? qk_b[o] : v_b[o - 512];
        #pragma unroll 4
        for (int i = 0; i < 32; i++) {
            int ml = qr + i * 4;
            float val = stg[ml * 65 + cc] + bias;
            int m = mb + ml;
            if (o < 512) {
                int bimg = m / PIX_PER_IMG;
                int hw = m - bimg * PIX_PER_IMG;
                int hh = hw / HWDIM, ww = hw - hh * HWDIM;
                int wi = bimg * 64 + (hh & 7) * 8 + (ww & 7);
                int n  = (hh >> 3) * 7 + (ww >> 3);
                if (o < 256)
                    g_q[(((size_t)wi * 8 + (o >> 5)) * 49 + n) * 32 + (o & 31)] = val * QSCALE;
                else {
                    int q2 = o - 256;
                    g_k[(((size_t)wi * 8 + (q2 >> 5)) * 49 + n) * 32 + (q2 & 31)] = val;
                }
            } else {
                g_v[(size_t)m * DE + (o - 512)] = val;
            }
        }
        __syncthreads();
    }
#undef G1_COPY
}

// ================= attention: one CTA per (window, head) =================
__global__ __launch_bounds__(128) void attn_kernel(const float* __restrict__ rpb) {
    int head = blockIdx.x;
    int wi   = blockIdx.y;
    int wp   = wi & 63;
    int bimg = wi >> 6;
    int tid  = threadIdx.x;

    __shared__ float Qs[49][33];
    __shared__ float Ks[49][33];
    __shared__ float Vs[49][64];
    __shared__ float Ss[49 * 49];
    __shared__ float rpbs[169];

    const float* qbase = g_q + ((size_t)wi * 8 + head) * 49 * 32;
    const float* kbase = g_k + ((size_t)wi * 8 + head) * 49 * 32;

    for (int i = tid; i < 49 * 32; i += 128) {
        Qs[i >> 5][i & 31] = qbase[i];
        Ks[i >> 5][i & 31] = kbase[i];
    }
    for (int i = tid; i < 169; i += 128)
        rpbs[i] = rpb[((size_t)wp * 169 + i) * 8 + head];
    for (int i = tid; i < 49 * 64; i += 128) {
        int n = i >> 6, vh = i & 63;
        int hh = (n / 7) * 8 + (wp >> 3), ww = (n % 7) * 8 + (wp & 7);
        size_t pix = (size_t)bimg * PIX_PER_IMG + hh * HWDIM + ww;
        Vs[n][vh] = g_v[pix * DE + head * 64 + vh];
    }
    __syncthreads();

    for (int i = tid; i < 49 * 49; i += 128) {
        int n = i / 49, m = i % 49;
        float s = 0.f;
        #pragma unroll
        for (int d = 0; d < 32; d++) s += Qs[n][d] * Ks[m][d];
        int i1 = n / 7, j1 = n % 7, i2 = m / 7, j2 = m % 7;
        s += rpbs[(i1 - i2 + 6) * 13 + (j1 - j2 + 6)];
        Ss[i] = s;
    }
    __syncthreads();

    if (tid < 49) {
        float* row = Ss + tid * 49;
        float mx = -1e30f;
        #pragma unroll 7
        for (int m = 0; m < 49; m++) mx = fmaxf(mx, row[m]);
        float sum = 0.f;
        #pragma unroll 7
        for (int m = 0; m < 49; m++) { float e = __expf(row[m] - mx); row[m] = e; sum += e; }
        float inv = 1.0f / sum;
        #pragma unroll 7
        for (int m = 0; m < 49; m++) row[m] *= inv;
    }
    __syncthreads();

    for (int i = tid; i < 49 * 64; i += 128) {
        int n = i >> 6, vh = i & 63;
        float o = 0.f;
        #pragma unroll 7
        for (int m = 0; m < 49; m++) o += Ss[n * 49 + m] * Vs[m][vh];
        int hh = (n / 7) * 8 + (wp >> 3), ww = (n % 7) * 8 + (wp & 7);
        size_t pix = (size_t)bimg * PIX_PER_IMG + hh * HWDIM + ww;
        g_v[pix * DE + head * 64 + vh] = o;
    }
}

// ================= post-LN stats over first 512 cols of g_v =================
__global__ __launch_bounds__(256) void ln2_stats_kernel() {
    int row = blockIdx.x * 8 + (threadIdx.x >> 5);
    int lane = threadIdx.x & 31;
    const float4* p = (const float4*)(g_v + (size_t)row * DE);
    float s = 0.f, ss = 0.f;
    #pragma unroll
    for (int j = 0; j < 4; j++) {
        float4 v = p[lane + 32 * j];
        s  += v.x + v.y + v.z + v.w;
        ss += v.x * v.x + v.y * v.y + v.z * v.z + v.w * v.w;
    }
    #pragma unroll
    for (int off = 16; off; off >>= 1) {
        s  += __shfl_down_sync(0xffffffffu, s, off);
        ss += __shfl_down_sync(0xffffffffu, ss, off);
    }
    if (lane == 0) {
        float mean = s * (1.0f / 512.0f);
        float var  = ss * (1.0f / 512.0f) - mean * mean;
        g_ln2m[row] = mean;
        g_ln2r[row] = rsqrtf(var + 1e-5f);
    }
}

// ================= GEMM2 (mma.sync fp16 x3): pre-converted frags =================
// M=NPIX, N=256, K=1024. BM=128, BN=128, BK=32.
__global__ __launch_bounds__(256) void gemm2_mma(
    const float* __restrict__ x,
    const float* __restrict__ proj_b,
    float* __restrict__ out)
{
    extern __shared__ char smem[];
    uint4* As = (uint4*)smem;
    uint2* Bs = (uint2*)(smem + 32768);

    const int tid = threadIdx.x, lane = tid & 31, wid = tid >> 5;
    const int wm = wid >> 1, wn = wid & 1;
    const int mb = blockIdx.x * 128, nb = blockIdx.y * 128;
    const int mtg0 = mb >> 4, ntg0 = nb >> 3;

    float acc[2][8][4];
    #pragma unroll
    for (int i = 0; i < 2; i++)
        #pragma unroll
        for (int j = 0; j < 8; j++)
            #pragma unroll
            for (int r = 0; r < 4; r++) acc[i][j][r] = 0.f;

    int a_lane[4], a_mt[4], a_ktl[4], a_p[4];
    #pragma unroll
    for (int j = 0; j < 4; j++) {
        int i = tid + j * 256;
        a_lane[j] = i & 31; a_mt[j] = (i >> 5) & 7; a_ktl[j] = (i >> 8) & 1; a_p[j] = i >> 9;
    }
    int b_lane[8], b_nt[8], b_ktl[8], b_p[8];
    #pragma unroll
    for (int j = 0; j < 8; j++) {
        int i = tid + j * 256;
        b_lane[j] = i & 31; b_nt[j] = (i >> 5) & 15; b_ktl[j] = (i >> 9) & 1; b_p[j] = i >> 10;
    }

#define G2_COPY(ST, KC) { \
    _Pragma("unroll") \
    for (int j = 0; j < 4; j++) { \
        const uint4* src = a_p[j] ? g_a2l : g_a2h; \
        As[AS_IDX(ST, a_p[j], a_ktl[j], a_mt[j]) + a_lane[j]] = \
            src[((size_t)(mtg0 + a_mt[j]) * 64 + (KC) * 2 + a_ktl[j]) * 32 + a_lane[j]]; \
    } \
    _Pragma("unroll") \
    for (int j = 0; j < 8; j++) { \
        const uint2* src = b_p[j] ? g_b2l : g_b2h; \
        Bs[BS_IDX(ST, b_p[j], b_ktl[j], b_nt[j]) + b_lane[j]] = \
            src[((size_t)(ntg0 + b_nt[j]) * 64 + (KC) * 2 + b_ktl[j]) * 32 + b_lane[j]]; \
    } }

    G2_COPY(0, 0);
    __syncthreads();

    const int NCH = 32;
    for (int kc = 0; kc < NCH; kc++) {
        int buf = kc & 1;
        if (kc + 1 < NCH) { G2_COPY(buf ^ 1, kc + 1); }
        #pragma unroll
        for (int kt = 0; kt < 2; kt++) {
            uint32_t ah[2][4], al[2][4], bh[8][2], bl[8][2];
            #pragma unroll
            for (int mti = 0; mti < 2; mti++) {
                *(uint4*)ah[mti] = As[AS_IDX(buf, 0, kt, wm * 2 + mti) + lane];
                *(uint4*)al[mti] = As[AS_IDX(buf, 1, kt, wm * 2 + mti) + lane];
            }
            #pragma unroll
            for (int nti = 0; nti < 8; nti++) {
                *(uint2*)bh[nti] = Bs[BS_IDX(buf, 0, kt, wn * 8 + nti) + lane];
                *(uint2*)bl[nti] = Bs[BS_IDX(buf, 1, kt, wn * 8 + nti) + lane];
            }
            #pragma unroll
            for (int mti = 0; mti < 2; mti++)
                #pragma unroll
                for (int nti = 0; nti < 8; nti++) {
                    mma16816(acc[mti][nti], ah[mti], bh[nti]);
                    mma16816(acc[mti][nti], al[mti], bh[nti]);
                    mma16816(acc[mti][nti], ah[mti], bl[nti]);
                }
        }
        __syncthreads();
    }

    // ---- epilogue: +bias +residual, rolled coalesced writes ----
    float* stg = (float*)smem;
    const int ml = tid & 127;
    const int chalf = tid >> 7;
    int m = mb + ml;
    int bimg = m / PIX_PER_IMG;
    int hw = m - bimg * PIX_PER_IMG;
    int hh = hw / HWDIM, ww = hw - hh * HWDIM;
    int h2 = hh + 2; if (h2 >= HWDIM) h2 -= HWDIM;
    int w2 = ww + 2; if (w2 >= HWDIM) w2 -= HWDIM;
    size_t inbase  = (size_t)bimg * C_IN * PIX_PER_IMG + hw;
    size_t outbase = (size_t)bimg * C_IN * PIX_PER_IMG + h2 * HWDIM + w2;

    for (int h = 0; h < 2; h++) {
        if (wn == h) {
            #pragma unroll
            for (int mti = 0; mti < 2; mti++)
                #pragma unroll
                for (int nti = 0; nti < 8; nti++) {
                    int r0 = wm * 32 + mti * 16 + (lane >> 2);
                    int c0 = nti * 8 + (lane & 3) * 2;
                    stg[r0 * 65 + c0]       = acc[mti][nti][0];
                    stg[r0 * 65 + c0 + 1]   = acc[mti][nti][1];
                    stg[(r0 + 8) * 65 + c0]     = acc[mti][nti][2];
                    stg[(r0 + 8) * 65 + c0 + 1] = acc[mti][nti][3];
                }
        }
        __syncthreads();
        #pragma unroll 8
        for (int i = 0; i < 32; i++) {
            int c = i * 2 + chalf;
            int o = nb + h * 64 + c;
            float val = stg[ml * 65 + c] + proj_b[o] + x[inbase + (size_t)o * PIX_PER_IMG];
            out[outbase + (size_t)o * PIX_PER_IMG] = val;
        }
        __syncthreads();
    }
#undef G2_COPY
}

// ================= launch =================
extern "C" void kernel_launch(void* const* d_in, const int* in_sizes, int n_in,
                              void* d_out, int out_size) {
    const float* x      = (const float*)d_in[0];
    const float* pre_g  = (const float*)d_in[1];
    const float* pre_b  = (const float*)d_in[2];
    const float* post_g = (const float*)d_in[3];
    const float* post_b = (const float*)d_in[4];
    const float* qk_w   = (const float*)d_in[5];
    const float* qk_b   = (const float*)d_in[6];
    const float* v_w    = (const float*)d_in[7];
    const float* v_b    = (const float*)d_in[8];
    const float* proj_w = (const float*)d_in[9];
    const float* proj_b = (const float*)d_in[10];
    const float* rpb    = (const float*)d_in[11];
    float* out = (float*)d_out;

    static int configured = 0;
    if (!configured) {
        cudaFuncSetAttribute(gemm1_mma, cudaFuncAttributeMaxDynamicSharedMemorySize, SMEM_BYTES);
        cudaFuncSetAttribute(gemm2_mma, cudaFuncAttributeMaxDynamicSharedMemorySize, SMEM_BYTES);
        configured = 1;
    }

    ln_stats_kernel<<<NPIX / 64, 256>>>(x);
    conv_w1<<<384, 256>>>(qk_w, v_w);
    conv_w2<<<256, 256>>>(proj_w);
    conv_a1<<<MT_TOT, 256>>>(x, pre_g, pre_b);
    gemm1_mma<<<dim3(12, NPIX / 128), 256, SMEM_BYTES>>>(qk_b, v_b);
    attn_kernel<<<dim3(NH, NWIN), 128>>>(rpb);
    ln2_stats_kernel<<<NPIX / 8, 256>>>();
    conv_a2<<<MT_TOT, 256>>>(post_g, post_b);
    gemm2_mma<<<dim3(NPIX / 128, 2), 256, SMEM_BYTES>>>(x, proj_b, out);
}